// round 2
// baseline (speedup 1.0000x reference)
#include <cuda_runtime.h>
#include <cstdint>

#define B_SZ  256
#define A_DIM 128
#define HID   512
#define TM    32          // (i,j) pairs per block
#define KT    16          // k-tile depth
#define NT    (HID / KT)  // 32 k-tiles

// Scratch for the x / y projections (device globals: no allocation allowed)
__device__ float g_hx[B_SZ * HID];  // hx = x @ Wx + b0
__device__ float g_hy[B_SZ * HID];  // hy = y @ Wy

// ---------------- packed fp32x2 helpers (sm_100+) ----------------
__device__ __forceinline__ unsigned long long pack2(float lo, float hi) {
    unsigned long long r;
    asm("mov.b64 %0, {%1, %2};" : "=l"(r) : "f"(lo), "f"(hi));
    return r;
}
__device__ __forceinline__ void unpack2(unsigned long long v, float& lo, float& hi) {
    asm("mov.b64 {%0, %1}, %2;" : "=f"(lo), "=f"(hi) : "l"(v));
}
__device__ __forceinline__ unsigned long long ffma2(unsigned long long a,
                                                    unsigned long long b,
                                                    unsigned long long c) {
    unsigned long long d;
    asm("fma.rn.f32x2 %0, %1, %2, %3;" : "=l"(d) : "l"(a), "l"(b), "l"(c));
    return d;
}
__device__ __forceinline__ void cp16(uint32_t dst_smem, const void* src) {
    asm volatile("cp.async.cg.shared.global [%0], [%1], 16;" :: "r"(dst_smem), "l"(src));
}

// ---------------- kernel 1: hx = x@Wx + b0, hy = y@Wy ----------------
__global__ void __launch_bounds__(128, 8) proj_kernel(
    const float* __restrict__ x, const float* __restrict__ y,
    const float* __restrict__ Wx, const float* __restrict__ Wy,
    const float* __restrict__ b0)
{
    __shared__ float sx[A_DIM];
    const int b = blockIdx.x, tid = threadIdx.x;

    const float* src; const float* W; float* dst; bool addb;
    if (b < B_SZ) { src = x + b * A_DIM;          W = Wx; dst = g_hx + b * HID;          addb = true;  }
    else          { src = y + (b - B_SZ) * A_DIM; W = Wy; dst = g_hy + (b - B_SZ) * HID; addb = false; }

    sx[tid] = src[tid];
    __syncthreads();

    const float4* W4 = (const float4*)W;   // [A_DIM][HID/4]
    float4 acc = make_float4(0.f, 0.f, 0.f, 0.f);
#pragma unroll 8
    for (int k = 0; k < A_DIM; ++k) {
        float xv = sx[k];
        float4 w = W4[k * (HID / 4) + tid];
        acc.x = fmaf(xv, w.x, acc.x);
        acc.y = fmaf(xv, w.y, acc.y);
        acc.z = fmaf(xv, w.z, acc.z);
        acc.w = fmaf(xv, w.w, acc.w);
    }
    if (addb) {
        float4 bb = ((const float4*)b0)[tid];
        acc.x += bb.x; acc.y += bb.y; acc.z += bb.z; acc.w += bb.w;
    }
    ((float4*)dst)[tid] = acc;
}

// ---------------- fused MLP building blocks ----------------
__device__ __forceinline__ void issue_wtile(const float4* __restrict__ Wg,
                                            float* wbuf, int t, int tid)
{
    uint32_t base = (uint32_t)__cvta_generic_to_shared(wbuf + (t & 1) * KT * HID);
#pragma unroll
    for (int e = 0; e < (KT * HID / 4) / 256; ++e) {   // 8 float4 per thread
        int f = tid + e * 256;                          // f = k*128 + c4
        cp16(base + f * 16, Wg + t * KT * (HID / 4) + f);
    }
    asm volatile("cp.async.commit_group;");
}

// GEMM layer: sh_out = relu(sh_in @ W + bias), sh_in/sh_out are [TM][HID] fp32 in SMEM.
__device__ __forceinline__ void mlp_layer(const float* __restrict__ W,
                                          const float* __restrict__ bias,
                                          const float* sh_in, float* sh_out,
                                          float* wbuf, int tid)
{
    const int tx = tid & 31;   // column group: cols tx*4 + g*128, g=0..3
    const int ty = tid >> 5;   // row group: rows ty*4 + rr
    const float4* Wg = (const float4*)W;

    float4 bq[4];
    const float4* b4 = (const float4*)bias;
#pragma unroll
    for (int g = 0; g < 4; ++g) bq[g] = b4[tx + g * 32];

    unsigned long long acc[4][4][2];
#pragma unroll
    for (int rr = 0; rr < 4; ++rr)
#pragma unroll
        for (int g = 0; g < 4; ++g) { acc[rr][g][0] = 0ull; acc[rr][g][1] = 0ull; }

    issue_wtile(Wg, wbuf, 0, tid);

    for (int t = 0; t < NT; ++t) {
        if (t + 1 < NT) {
            issue_wtile(Wg, wbuf, t + 1, tid);
            asm volatile("cp.async.wait_group 1;");
        } else {
            asm volatile("cp.async.wait_group 0;");
        }
        __syncthreads();

        const ulonglong2* wb = (const ulonglong2*)(wbuf + (t & 1) * KT * HID);
#pragma unroll
        for (int k = 0; k < KT; ++k) {
            const int kk = t * KT + k;
            unsigned long long hv[4];
#pragma unroll
            for (int rr = 0; rr < 4; ++rr) {
                float h = sh_in[(ty * 4 + rr) * HID + kk];   // warp-broadcast LDS
                hv[rr] = pack2(h, h);
            }
#pragma unroll
            for (int g = 0; g < 4; ++g) {
                ulonglong2 wq = wb[k * 128 + tx + g * 32];   // LDS.128, conflict-free
#pragma unroll
                for (int rr = 0; rr < 4; ++rr) {
                    acc[rr][g][0] = ffma2(hv[rr], wq.x, acc[rr][g][0]);
                    acc[rr][g][1] = ffma2(hv[rr], wq.y, acc[rr][g][1]);
                }
            }
        }
        __syncthreads();
    }

    // epilogue: bias + relu -> sh_out
    float4* out4 = (float4*)sh_out;
#pragma unroll
    for (int rr = 0; rr < 4; ++rr)
#pragma unroll
        for (int g = 0; g < 4; ++g) {
            float a0, a1, a2, a3;
            unpack2(acc[rr][g][0], a0, a1);
            unpack2(acc[rr][g][1], a2, a3);
            a0 = fmaxf(a0 + bq[g].x, 0.f);
            a1 = fmaxf(a1 + bq[g].y, 0.f);
            a2 = fmaxf(a2 + bq[g].z, 0.f);
            a3 = fmaxf(a3 + bq[g].w, 0.f);
            out4[(ty * 4 + rr) * 128 + tx + g * 32] = make_float4(a0, a1, a2, a3);
        }
    __syncthreads();
}

// ---------------- fused kernel: h0 -> L1 -> L2 -> scores ----------------
__global__ void __launch_bounds__(256, 1) fused_kernel(
    const float* __restrict__ W1, const float* __restrict__ b1,
    const float* __restrict__ W2, const float* __restrict__ b2,
    const float* __restrict__ W3, const float* __restrict__ b3,
    float* __restrict__ out)
{
    extern __shared__ float smem[];
    float* bufA = smem;                    // TM*HID = 16384 floats
    float* bufB = smem + TM * HID;         // 16384 floats
    float* wbuf = smem + 2 * TM * HID;     // 2*KT*HID = 16384 floats

    const int tid = threadIdx.x;
    const int blk = blockIdx.x;
    const int i   = blk >> 3;              // 8 blocks per i (256/TM)
    const int j0  = (blk & 7) * TM;

    // h0 = relu(hx[i] + hy[j] (+b0 folded into hx))
    const float4* hx4 = (const float4*)g_hx + i * (HID / 4);
    const float4* hy4 = (const float4*)g_hy;
    float4* bufA4 = (float4*)bufA;
#pragma unroll
    for (int e = 0; e < (TM * HID / 4) / 256; ++e) {   // 16 float4 per thread
        int f = tid + e * 256;
        int r = f >> 7, c4 = f & 127;
        float4 a = hx4[c4];
        float4 b = hy4[(j0 + r) * (HID / 4) + c4];
        bufA4[f] = make_float4(fmaxf(a.x + b.x, 0.f), fmaxf(a.y + b.y, 0.f),
                               fmaxf(a.z + b.z, 0.f), fmaxf(a.w + b.w, 0.f));
    }
    __syncthreads();

    mlp_layer(W1, b1, bufA, bufB, wbuf, tid);   // h1 = relu(h0@W1+b1)
    mlp_layer(W2, b2, bufB, bufA, wbuf, tid);   // h2 = relu(h1@W2+b2)

    // scores = h2 @ W3 + b3 ; each warp handles 4 rows
    const int wid = tid >> 5, lane = tid & 31;
    float w3v[16];
#pragma unroll
    for (int e = 0; e < 16; ++e) w3v[e] = W3[lane + e * 32];

#pragma unroll
    for (int rr = 0; rr < 4; ++rr) {
        const int r = wid * 4 + rr;
        float s = 0.f;
#pragma unroll
        for (int e = 0; e < 16; ++e)
            s = fmaf(bufA[r * HID + lane + e * 32], w3v[e], s);
#pragma unroll
        for (int off = 16; off; off >>= 1)
            s += __shfl_xor_sync(0xffffffffu, s, off);
        if (lane == 0) out[i * B_SZ + j0 + r] = s + b3[0];
    }
}

// ---------------- launch ----------------
extern "C" void kernel_launch(void* const* d_in, const int* in_sizes, int n_in,
                              void* d_out, int out_size)
{
    const float* x  = (const float*)d_in[0];
    const float* y  = (const float*)d_in[1];
    const float* Wx = (const float*)d_in[2];
    const float* Wy = (const float*)d_in[3];
    const float* b0 = (const float*)d_in[4];
    const float* W1 = (const float*)d_in[5];
    const float* b1 = (const float*)d_in[6];
    const float* W2 = (const float*)d_in[7];
    const float* b2 = (const float*)d_in[8];
    const float* W3 = (const float*)d_in[9];
    const float* b3 = (const float*)d_in[10];
    float* out = (float*)d_out;

    const int smem_bytes = 3 * TM * HID * (int)sizeof(float);  // 196608
    cudaFuncSetAttribute(fused_kernel, cudaFuncAttributeMaxDynamicSharedMemorySize, smem_bytes);

    proj_kernel<<<2 * B_SZ, 128>>>(x, y, Wx, Wy, b0);
    fused_kernel<<<(B_SZ * B_SZ) / TM, 256, smem_bytes>>>(W1, b1, W2, b2, W3, b3, out);
}

// round 4
// speedup vs baseline: 2.1052x; 2.1052x over previous
#include <cuda_runtime.h>
#include <cuda_bf16.h>
#include <cstdint>

#define HID    512
#define BSZ    256
#define NROWS  (BSZ * BSZ)      // 65536
#define TILE_M 128
#define TILE_N 128
#define KC     32               // k per chunk
#define NCH    (HID / KC)       // 16 chunks

// Dynamic SMEM: 2 stages x (Ahi 8K | Alo 8K | Bhi 8K | Blo 8K) = 65536 B
#define STAGE_BYTES 32768
#define SMEM_BYTES  65536

// ---------------- device scratch ----------------
__device__ __align__(128) float g_hx[BSZ * HID];
__device__ __align__(128) float g_hy[BSZ * HID];
__device__ __align__(128) __nv_bfloat16 g_ahi[NROWS * HID];
__device__ __align__(128) __nv_bfloat16 g_alo[NROWS * HID];
__device__ __align__(128) __nv_bfloat16 g_whi[2][HID * HID]; // [n][k]
__device__ __align__(128) __nv_bfloat16 g_wlo[2][HID * HID];

// ---------------- helpers ----------------
__device__ __forceinline__ uint32_t smem_u32(const void* p) {
    return (uint32_t)__cvta_generic_to_shared(p);
}
__device__ __forceinline__ void cp16(uint32_t dst, const void* src) {
    asm volatile("cp.async.cg.shared.global [%0], [%1], 16;" :: "r"(dst), "l"(src));
}
#define CP_COMMIT() asm volatile("cp.async.commit_group;")
#define CP_WAIT(n)  asm volatile("cp.async.wait_group %0;" :: "n"(n))

__device__ __forceinline__ uint32_t swz(uint32_t o) { return o ^ ((o >> 3) & 0x30); }

__device__ __forceinline__ void ldsm4(uint32_t& r0, uint32_t& r1, uint32_t& r2, uint32_t& r3,
                                      uint32_t addr) {
    asm volatile("ldmatrix.sync.aligned.m8n8.x4.shared.b16 {%0,%1,%2,%3}, [%4];"
                 : "=r"(r0), "=r"(r1), "=r"(r2), "=r"(r3) : "r"(addr));
}
__device__ __forceinline__ void mma16816(float* c, const uint32_t* a, uint32_t b0, uint32_t b1) {
    asm volatile("mma.sync.aligned.m16n8k16.row.col.f32.bf16.bf16.f32 "
                 "{%0,%1,%2,%3}, {%4,%5,%6,%7}, {%8,%9}, {%0,%1,%2,%3};"
                 : "+f"(c[0]), "+f"(c[1]), "+f"(c[2]), "+f"(c[3])
                 : "r"(a[0]), "r"(a[1]), "r"(a[2]), "r"(a[3]), "r"(b0), "r"(b1));
}
__device__ __forceinline__ uint32_t pack_bf2(float v0, float v1) {
    __nv_bfloat16 b0 = __float2bfloat16(v0), b1 = __float2bfloat16(v1);
    return ((uint32_t)__bfloat16_as_ushort(b1) << 16) | __bfloat16_as_ushort(b0);
}

// ---------------- prep: split+transpose W1/W2 ----------------
__global__ void prep_w_kernel(const float* __restrict__ W1, const float* __restrict__ W2) {
    int n = blockIdx.x & 511;
    int which = blockIdx.x >> 9;
    const float* W = which ? W2 : W1;
    for (int k = threadIdx.x; k < HID; k += blockDim.x) {
        float w = W[k * HID + n];
        __nv_bfloat16 h = __float2bfloat16(w);
        g_whi[which][n * HID + k] = h;
        g_wlo[which][n * HID + k] = __float2bfloat16(w - __bfloat162float(h));
    }
}

// ---------------- proj: hx = x@Wx + b0, hy = y@Wy ----------------
__global__ void __launch_bounds__(128, 8) proj_kernel(
    const float* __restrict__ x, const float* __restrict__ y,
    const float* __restrict__ Wx, const float* __restrict__ Wy,
    const float* __restrict__ b0)
{
    __shared__ float sx[128];
    const int b = blockIdx.x, tid = threadIdx.x;
    const float* src; const float* W; float* dst; bool addb;
    if (b < BSZ) { src = x + b * 128;         W = Wx; dst = g_hx + b * HID;         addb = true;  }
    else         { src = y + (b - BSZ) * 128; W = Wy; dst = g_hy + (b - BSZ) * HID; addb = false; }
    sx[tid] = src[tid];
    __syncthreads();
    const float4* W4 = (const float4*)W;
    float4 acc = make_float4(0.f, 0.f, 0.f, 0.f);
#pragma unroll 8
    for (int k = 0; k < 128; ++k) {
        float xv = sx[k];
        float4 w = W4[k * (HID / 4) + tid];
        acc.x = fmaf(xv, w.x, acc.x); acc.y = fmaf(xv, w.y, acc.y);
        acc.z = fmaf(xv, w.z, acc.z); acc.w = fmaf(xv, w.w, acc.w);
    }
    if (addb) {
        float4 bb = ((const float4*)b0)[tid];
        acc.x += bb.x; acc.y += bb.y; acc.z += bb.z; acc.w += bb.w;
    }
    ((float4*)dst)[tid] = acc;
}

// ---------------- h0 = relu(hx[i] + hy[j]) -> bf16 hi/lo ----------------
__global__ void __launch_bounds__(256) h0_kernel() {
    const int r0 = blockIdx.x * 8;
#pragma unroll
    for (int e = 0; e < 8; ++e) {
        int idx = threadIdx.x + 256 * e;
        int rl = idx >> 8;
        int c2 = (idx & 255) * 2;
        int r = r0 + rl, i = r >> 8, j = r & 255;
        float2 a = *(const float2*)(g_hx + i * HID + c2);
        float2 b = *(const float2*)(g_hy + j * HID + c2);
        float v0 = fmaxf(a.x + b.x, 0.f), v1 = fmaxf(a.y + b.y, 0.f);
        __nv_bfloat16 h0 = __float2bfloat16(v0), h1 = __float2bfloat16(v1);
        size_t o = (size_t)r * HID + c2;
        *(uint32_t*)(g_ahi + o) = ((uint32_t)__bfloat16_as_ushort(h1) << 16) | __bfloat16_as_ushort(h0);
        *(uint32_t*)(g_alo + o) = pack_bf2(v0 - __bfloat162float(h0), v1 - __bfloat162float(h1));
    }
}

// ---------------- GEMM layer: A <- relu(A @ W^T + b), split-bf16 x3 via mma.sync ----------------
__global__ void __launch_bounds__(256, 1) layer_kernel(int which, const float* __restrict__ bias) {
    extern __shared__ __align__(1024) char smem[];
    const uint32_t sbase = smem_u32(smem);
    const int tid = threadIdx.x, wid = tid >> 5, lane = tid & 31;
    const int warp_m = wid & 1;        // 2 x 64-row strips
    const int warp_n = wid >> 1;       // 4 x 32-col strips
    const int r0 = blockIdx.x >> 2;    // m-tile
    const int row0 = r0 * TILE_M;
    const int n0 = (blockIdx.x & 3) * TILE_N;
    const __nv_bfloat16* __restrict__ Whi = g_whi[which];
    const __nv_bfloat16* __restrict__ Wlo = g_wlo[which];

    // per-thread ldmatrix base addresses (swizzle bits depend only on lane)
    const uint32_t oA = (uint32_t)((warp_m * 64 + (lane & 15)) * 64 + ((lane >> 4) & 1) * 16);
    const uint32_t aA = swz(oA);                              // + mg*1024, ^ k16*32
    const int nloc = (lane & 7) + ((lane >> 4) << 3);
    const uint32_t oB = (uint32_t)((warp_n * 32 + nloc) * 64 + ((lane >> 3) & 1) * 16);
    const uint32_t aB = swz(oB);                              // + ng*1024, ^ k16*32

    float acc[4][4][4];
#pragma unroll
    for (int mg = 0; mg < 4; ++mg)
#pragma unroll
        for (int n8 = 0; n8 < 4; ++n8)
#pragma unroll
            for (int c = 0; c < 4; ++c) acc[mg][n8][c] = 0.f;

    // chunk loader: 2048 cp16 / 256 thr = 8 each
    auto load_chunk = [&](int t, int s) {
        uint32_t sb = sbase + s * STAGE_BYTES;
#pragma unroll
        for (int e = 0; e < 8; ++e) {
            int idx = tid + 256 * e;
            int part = idx >> 9;             // 0:Ahi 1:Alo 2:Bhi 3:Blo
            int r = (idx >> 2) & 127;
            int u = idx & 3;
            uint32_t off = sb + part * 8192 + swz((uint32_t)(r * 64 + u * 16));
            size_t go;
            const __nv_bfloat16* src;
            if (part < 2) {
                go = (size_t)(row0 + r) * HID + t * KC + u * 8;
                src = part ? g_alo : g_ahi;
            } else {
                go = (size_t)(n0 + r) * HID + t * KC + u * 8;
                src = (part == 2) ? Whi : Wlo;
            }
            cp16(off, src + go);
        }
        CP_COMMIT();
    };

    load_chunk(0, 0);

    for (int t = 0; t < NCH; ++t) {
        if (t + 1 < NCH) { load_chunk(t + 1, (t + 1) & 1); CP_WAIT(1); }
        else             { CP_WAIT(0); }
        __syncthreads();

        const uint32_t stg = sbase + (t & 1) * STAGE_BYTES;
#pragma unroll
        for (int k16 = 0; k16 < 2; ++k16) {
            const uint32_t ko = (uint32_t)(k16 << 5);
            uint32_t ah[4][4], al[4][4], bh[2][4], bl[2][4];
#pragma unroll
            for (int mg = 0; mg < 4; ++mg) {
                uint32_t base = (stg + aA + mg * 1024) ^ ko;
                ldsm4(ah[mg][0], ah[mg][1], ah[mg][2], ah[mg][3], base);
                ldsm4(al[mg][0], al[mg][1], al[mg][2], al[mg][3], base + 8192);
            }
#pragma unroll
            for (int ng = 0; ng < 2; ++ng) {
                uint32_t base = (stg + 16384 + aB + ng * 1024) ^ ko;
                ldsm4(bh[ng][0], bh[ng][1], bh[ng][2], bh[ng][3], base);
                ldsm4(bl[ng][0], bl[ng][1], bl[ng][2], bl[ng][3], base + 8192);
            }
#pragma unroll
            for (int mg = 0; mg < 4; ++mg)
#pragma unroll
                for (int ng = 0; ng < 2; ++ng)
#pragma unroll
                    for (int j = 0; j < 2; ++j) {
                        float* c = acc[mg][ng * 2 + j];
                        mma16816(c, ah[mg], bh[ng][2 * j], bh[ng][2 * j + 1]);  // hi*hi
                        mma16816(c, al[mg], bh[ng][2 * j], bh[ng][2 * j + 1]);  // lo*hi
                        mma16816(c, ah[mg], bl[ng][2 * j], bl[ng][2 * j + 1]);  // hi*lo
                    }
        }
        __syncthreads();
    }

    // epilogue: bias + relu -> split bf16 hi/lo -> global
#pragma unroll
    for (int n8 = 0; n8 < 4; ++n8) {
        const int col = n0 + warp_n * 32 + n8 * 8 + (lane & 3) * 2;
        float2 bq = *(const float2*)(bias + col);
#pragma unroll
        for (int mg = 0; mg < 4; ++mg) {
            const int row = row0 + warp_m * 64 + mg * 16 + (lane >> 2);
            float* c = acc[mg][n8];
#pragma unroll
            for (int h = 0; h < 2; ++h) {
                float v0 = fmaxf(c[2 * h]     + bq.x, 0.f);
                float v1 = fmaxf(c[2 * h + 1] + bq.y, 0.f);
                __nv_bfloat16 b0 = __float2bfloat16(v0), b1 = __float2bfloat16(v1);
                size_t o = (size_t)(row + h * 8) * HID + col;
                *(uint32_t*)(g_ahi + o) =
                    ((uint32_t)__bfloat16_as_ushort(b1) << 16) | __bfloat16_as_ushort(b0);
                *(uint32_t*)(g_alo + o) =
                    pack_bf2(v0 - __bfloat162float(b0), v1 - __bfloat162float(b1));
            }
        }
    }
}

// ---------------- final: out[r] = h2[r,:] . W3 + b3 ----------------
__global__ void __launch_bounds__(256) final_kernel(const float* __restrict__ W3,
                                                    const float* __restrict__ b3,
                                                    float* __restrict__ out) {
    __shared__ float sw[HID];
    for (int k = threadIdx.x; k < HID; k += blockDim.x) sw[k] = W3[k];
    __syncthreads();
    const int wid = threadIdx.x >> 5, lane = threadIdx.x & 31;
    const size_t r = (size_t)blockIdx.x * 8 + wid;
    const uint4* ph = (const uint4*)(g_ahi + r * HID);
    const uint4* pl = (const uint4*)(g_alo + r * HID);
    float s = 0.f;
#pragma unroll
    for (int u = 0; u < 2; ++u) {
        int q = lane + 32 * u;
        uint4 a = ph[q], b = pl[q];
        const uint32_t* aw = &a.x;
        const uint32_t* bw = &b.x;
#pragma unroll
        for (int w = 0; w < 4; ++w) {
            int k = q * 8 + 2 * w;
            float v0 = __bfloat162float(__ushort_as_bfloat16((unsigned short)(aw[w] & 0xFFFF)))
                     + __bfloat162float(__ushort_as_bfloat16((unsigned short)(bw[w] & 0xFFFF)));
            float v1 = __bfloat162float(__ushort_as_bfloat16((unsigned short)(aw[w] >> 16)))
                     + __bfloat162float(__ushort_as_bfloat16((unsigned short)(bw[w] >> 16)));
            s = fmaf(v0, sw[k], s);
            s = fmaf(v1, sw[k + 1], s);
        }
    }
#pragma unroll
    for (int off = 16; off; off >>= 1) s += __shfl_xor_sync(0xffffffffu, s, off);
    if (lane == 0) out[r] = s + b3[0];
}

// ---------------- launch ----------------
extern "C" void kernel_launch(void* const* d_in, const int* in_sizes, int n_in,
                              void* d_out, int out_size)
{
    const float* x  = (const float*)d_in[0];
    const float* y  = (const float*)d_in[1];
    const float* Wx = (const float*)d_in[2];
    const float* Wy = (const float*)d_in[3];
    const float* b0 = (const float*)d_in[4];
    const float* W1 = (const float*)d_in[5];
    const float* b1 = (const float*)d_in[6];
    const float* W2 = (const float*)d_in[7];
    const float* b2 = (const float*)d_in[8];
    const float* W3 = (const float*)d_in[9];
    const float* b3 = (const float*)d_in[10];
    float* out = (float*)d_out;

    cudaFuncSetAttribute(layer_kernel, cudaFuncAttributeMaxDynamicSharedMemorySize, SMEM_BYTES);

    prep_w_kernel<<<1024, 256>>>(W1, W2);
    proj_kernel<<<2 * BSZ, 128>>>(x, y, Wx, Wy, b0);
    h0_kernel<<<NROWS / 8, 256>>>();
    layer_kernel<<<(NROWS / TILE_M) * (HID / TILE_N), 256, SMEM_BYTES>>>(0, b1);
    layer_kernel<<<(NROWS / TILE_M) * (HID / TILE_N), 256, SMEM_BYTES>>>(1, b2);
    final_kernel<<<NROWS / 8, 256>>>(W3, b3, out);
}

// round 5
// speedup vs baseline: 6.1293x; 2.9115x over previous
#include <cuda_runtime.h>
#include <cuda_fp16.h>
#include <cstdint>

#define HID    512
#define BSZ    256
#define NROWS  (BSZ * BSZ)      // 65536
#define TILE_M 128
#define TILE_N 128
#define KC     64               // k per chunk (128B rows)
#define NCH    (HID / KC)       // 8 chunks

// Stage: A(128x64 fp16)=16K | Whi(128x64)=16K | Wlo(128x64)=16K = 48K; 2 stages
#define STAGE_BYTES 49152
#define SMEM_BYTES  98304

// ---------------- device scratch ----------------
__device__ __align__(128) float g_hx[BSZ * HID];
__device__ __align__(128) float g_hy[BSZ * HID];
__device__ __align__(128) __half g_ah[NROWS * HID];          // activations, fp16
__device__ __align__(128) __half g_wh[2][HID * HID];         // [n][k] transposed, hi
__device__ __align__(128) __half g_wl[2][HID * HID];         // lo residual

// ---------------- helpers ----------------
__device__ __forceinline__ uint32_t smem_u32(const void* p) {
    return (uint32_t)__cvta_generic_to_shared(p);
}
__device__ __forceinline__ void cp16(uint32_t dst, const void* src) {
    asm volatile("cp.async.cg.shared.global [%0], [%1], 16;" :: "r"(dst), "l"(src));
}
#define CP_COMMIT() asm volatile("cp.async.commit_group;")
#define CP_WAIT(n)  asm volatile("cp.async.wait_group %0;" :: "n"(n))

// SW128 swizzle for 128B rows
__device__ __forceinline__ uint32_t swz(uint32_t o) { return o ^ ((o >> 3) & 0x70); }

__device__ __forceinline__ void ldsm4(uint32_t& r0, uint32_t& r1, uint32_t& r2, uint32_t& r3,
                                      uint32_t addr) {
    asm volatile("ldmatrix.sync.aligned.m8n8.x4.shared.b16 {%0,%1,%2,%3}, [%4];"
                 : "=r"(r0), "=r"(r1), "=r"(r2), "=r"(r3) : "r"(addr));
}
__device__ __forceinline__ void mma16816(float* c, const uint32_t* a, uint32_t b0, uint32_t b1) {
    asm volatile("mma.sync.aligned.m16n8k16.row.col.f32.f16.f16.f32 "
                 "{%0,%1,%2,%3}, {%4,%5,%6,%7}, {%8,%9}, {%0,%1,%2,%3};"
                 : "+f"(c[0]), "+f"(c[1]), "+f"(c[2]), "+f"(c[3])
                 : "r"(a[0]), "r"(a[1]), "r"(a[2]), "r"(a[3]), "r"(b0), "r"(b1));
}

// ---------------- prep: split+transpose W1/W2 to fp16 hi/lo ----------------
__global__ void prep_w_kernel(const float* __restrict__ W1, const float* __restrict__ W2) {
    int n = blockIdx.x & 511;
    int which = blockIdx.x >> 9;
    const float* W = which ? W2 : W1;
    for (int k = threadIdx.x; k < HID; k += blockDim.x) {
        float w = W[k * HID + n];
        __half h = __float2half(w);
        g_wh[which][n * HID + k] = h;
        g_wl[which][n * HID + k] = __float2half(w - __half2float(h));
    }
}

// ---------------- proj: hx = x@Wx + b0, hy = y@Wy ----------------
__global__ void __launch_bounds__(128, 8) proj_kernel(
    const float* __restrict__ x, const float* __restrict__ y,
    const float* __restrict__ Wx, const float* __restrict__ Wy,
    const float* __restrict__ b0)
{
    __shared__ float sx[128];
    const int b = blockIdx.x, tid = threadIdx.x;
    const float* src; const float* W; float* dst; bool addb;
    if (b < BSZ) { src = x + b * 128;         W = Wx; dst = g_hx + b * HID;         addb = true;  }
    else         { src = y + (b - BSZ) * 128; W = Wy; dst = g_hy + (b - BSZ) * HID; addb = false; }
    sx[tid] = src[tid];
    __syncthreads();
    const float4* W4 = (const float4*)W;
    float4 acc = make_float4(0.f, 0.f, 0.f, 0.f);
#pragma unroll 8
    for (int k = 0; k < 128; ++k) {
        float xv = sx[k];
        float4 w = W4[k * (HID / 4) + tid];
        acc.x = fmaf(xv, w.x, acc.x); acc.y = fmaf(xv, w.y, acc.y);
        acc.z = fmaf(xv, w.z, acc.z); acc.w = fmaf(xv, w.w, acc.w);
    }
    if (addb) {
        float4 bb = ((const float4*)b0)[tid];
        acc.x += bb.x; acc.y += bb.y; acc.z += bb.z; acc.w += bb.w;
    }
    ((float4*)dst)[tid] = acc;
}

// ---------------- h0 = relu(hx[i] + hy[j]) -> fp16 ----------------
__global__ void __launch_bounds__(256) h0_kernel() {
    const int r0 = blockIdx.x * 8;
#pragma unroll
    for (int e = 0; e < 8; ++e) {
        int idx = threadIdx.x + 256 * e;
        int rl = idx >> 8;
        int c2 = (idx & 255) * 2;
        int r = r0 + rl, i = r >> 8, j = r & 255;
        float2 a = *(const float2*)(g_hx + i * HID + c2);
        float2 b = *(const float2*)(g_hy + j * HID + c2);
        float v0 = fmaxf(a.x + b.x, 0.f), v1 = fmaxf(a.y + b.y, 0.f);
        *(__half2*)(g_ah + (size_t)r * HID + c2) = __floats2half2_rn(v0, v1);
    }
}

// ---------------- GEMM layer: A <- relu(A @ W^T + b), fp16 2-product ----------------
__global__ void __launch_bounds__(256, 2) layer_kernel(int which, const float* __restrict__ bias) {
    extern __shared__ __align__(1024) char smem[];
    const uint32_t sbase = smem_u32(smem);
    const int tid = threadIdx.x, wid = tid >> 5, lane = tid & 31;
    const int warp_m = wid & 1;        // 2 x 64-row strips
    const int warp_n = wid >> 1;       // 4 x 32-col strips
    const int row0 = (blockIdx.x >> 2) * TILE_M;
    const int n0 = (blockIdx.x & 3) * TILE_N;
    const __half* __restrict__ Whi = g_wh[which];
    const __half* __restrict__ Wlo = g_wl[which];

    // ldmatrix per-thread addresses (swizzle bits depend only on lane)
    const uint32_t aA = swz((uint32_t)((warp_m * 64 + (lane & 15)) * 128 + ((lane >> 4) & 1) * 16));
    const int nloc = (lane & 7) + ((lane >> 4) << 3);
    const uint32_t aB = swz((uint32_t)((warp_n * 32 + nloc) * 128 + ((lane >> 3) & 1) * 16));

    float acc[4][4][4];
#pragma unroll
    for (int mg = 0; mg < 4; ++mg)
#pragma unroll
        for (int n8 = 0; n8 < 4; ++n8)
#pragma unroll
            for (int c = 0; c < 4; ++c) acc[mg][n8][c] = 0.f;

    // chunk loader: 3072 cp16 / 256 thr = 12 each (part uniform per e)
    auto load_chunk = [&](int t, int s) {
        uint32_t sb = sbase + s * STAGE_BYTES;
#pragma unroll
        for (int e = 0; e < 12; ++e) {
            int idx = tid + 256 * e;
            int part = idx >> 10;            // 0:A 1:Whi 2:Wlo
            int r = (idx >> 3) & 127;
            int u = idx & 7;
            uint32_t dst = sb + part * 16384 + swz((uint32_t)(r * 128 + u * 16));
            const __half* src = (part == 0) ? g_ah : ((part == 1) ? Whi : Wlo);
            int rbase = (part == 0) ? row0 : n0;
            cp16(dst, src + (size_t)(rbase + r) * HID + t * KC + u * 8);
        }
        CP_COMMIT();
    };

    load_chunk(0, 0);

#pragma unroll 1
    for (int t = 0; t < NCH; ++t) {
        if (t + 1 < NCH) { load_chunk(t + 1, (t + 1) & 1); CP_WAIT(1); }
        else             { CP_WAIT(0); }
        __syncthreads();

        const uint32_t stg = sbase + (t & 1) * STAGE_BYTES;
#pragma unroll
        for (int k16 = 0; k16 < 4; ++k16) {
            const uint32_t ko = (uint32_t)(k16 << 5);
            uint32_t bh[2][4], bl[2][4];
#pragma unroll
            for (int ng = 0; ng < 2; ++ng) {
                uint32_t base = (stg + 16384 + aB + ng * 2048) ^ ko;
                ldsm4(bh[ng][0], bh[ng][1], bh[ng][2], bh[ng][3], base);
                ldsm4(bl[ng][0], bl[ng][1], bl[ng][2], bl[ng][3], base + 16384);
            }
#pragma unroll
            for (int mg = 0; mg < 4; ++mg) {
                uint32_t a[4];
                ldsm4(a[0], a[1], a[2], a[3], (stg + aA + mg * 2048) ^ ko);
#pragma unroll
                for (int ng = 0; ng < 2; ++ng)
#pragma unroll
                    for (int j = 0; j < 2; ++j) {
                        float* c = acc[mg][ng * 2 + j];
                        mma16816(c, a, bh[ng][2 * j], bh[ng][2 * j + 1]);   // a * w_hi
                        mma16816(c, a, bl[ng][2 * j], bl[ng][2 * j + 1]);   // a * w_lo
                    }
            }
        }
        __syncthreads();
    }

    // epilogue: bias + relu -> fp16 -> global
#pragma unroll
    for (int n8 = 0; n8 < 4; ++n8) {
        const int col = n0 + warp_n * 32 + n8 * 8 + (lane & 3) * 2;
        float2 bq = *(const float2*)(bias + col);
#pragma unroll
        for (int mg = 0; mg < 4; ++mg) {
            const int row = row0 + warp_m * 64 + mg * 16 + (lane >> 2);
            float* c = acc[mg][n8];
#pragma unroll
            for (int h = 0; h < 2; ++h) {
                float v0 = fmaxf(c[2 * h]     + bq.x, 0.f);
                float v1 = fmaxf(c[2 * h + 1] + bq.y, 0.f);
                *(__half2*)(g_ah + (size_t)(row + h * 8) * HID + col) = __floats2half2_rn(v0, v1);
            }
        }
    }
}

// ---------------- final: out[r] = h2[r,:] . W3 + b3 ----------------
__global__ void __launch_bounds__(256) final_kernel(const float* __restrict__ W3,
                                                    const float* __restrict__ b3,
                                                    float* __restrict__ out) {
    __shared__ float sw[HID];
    for (int k = threadIdx.x; k < HID; k += blockDim.x) sw[k] = W3[k];
    __syncthreads();
    const int wid = threadIdx.x >> 5, lane = threadIdx.x & 31;
    const size_t r = (size_t)blockIdx.x * 8 + wid;
    const uint4* ph = (const uint4*)(g_ah + r * HID);   // 8 halves per uint4
    float s = 0.f;
#pragma unroll
    for (int u = 0; u < 2; ++u) {
        int q = lane + 32 * u;
        uint4 a = ph[q];
        const uint32_t* aw = &a.x;
#pragma unroll
        for (int w = 0; w < 4; ++w) {
            int k = q * 8 + 2 * w;
            __half2 hv = *(const __half2*)&aw[w];
            float2 v = __half22float2(hv);
            s = fmaf(v.x, sw[k], s);
            s = fmaf(v.y, sw[k + 1], s);
        }
    }
#pragma unroll
    for (int off = 16; off; off >>= 1) s += __shfl_xor_sync(0xffffffffu, s, off);
    if (lane == 0) out[r] = s + b3[0];
}

// ---------------- launch ----------------
extern "C" void kernel_launch(void* const* d_in, const int* in_sizes, int n_in,
                              void* d_out, int out_size)
{
    const float* x  = (const float*)d_in[0];
    const float* y  = (const float*)d_in[1];
    const float* Wx = (const float*)d_in[2];
    const float* Wy = (const float*)d_in[3];
    const float* b0 = (const float*)d_in[4];
    const float* W1 = (const float*)d_in[5];
    const float* b1 = (const float*)d_in[6];
    const float* W2 = (const float*)d_in[7];
    const float* b2 = (const float*)d_in[8];
    const float* W3 = (const float*)d_in[9];
    const float* b3 = (const float*)d_in[10];
    float* out = (float*)d_out;

    cudaFuncSetAttribute(layer_kernel, cudaFuncAttributeMaxDynamicSharedMemorySize, SMEM_BYTES);

    prep_w_kernel<<<1024, 256>>>(W1, W2);
    proj_kernel<<<2 * BSZ, 128>>>(x, y, Wx, Wy, b0);
    h0_kernel<<<NROWS / 8, 256>>>();
    layer_kernel<<<(NROWS / TILE_M) * (HID / TILE_N), 256, SMEM_BYTES>>>(0, b1);
    layer_kernel<<<(NROWS / TILE_M) * (HID / TILE_N), 256, SMEM_BYTES>>>(1, b2);
    final_kernel<<<NROWS / 8, 256>>>(W3, b3, out);
}

// round 6
// speedup vs baseline: 6.2941x; 1.0269x over previous
#include <cuda_runtime.h>
#include <cuda_fp16.h>
#include <cstdint>

#define HID    512
#define BSZ    256
#define NROWS  (BSZ * BSZ)      // 65536
#define TILE_M 128
#define TILE_N 128
#define KC     64               // k per chunk (128B rows)
#define NCH    (HID / KC)       // 8 chunks

// Stage: A(128x64 fp16)=16K | Whi=16K | Wlo=16K = 48K; 2 stages; + s_hx 2K
#define STAGE_BYTES 49152
#define SMEM_HX     98304
#define SMEM_BYTES  100352

// ---------------- device scratch ----------------
__device__ __align__(128) float g_hx[BSZ * HID];
__device__ __align__(128) float g_hy[BSZ * HID];
__device__ __align__(128) __half g_ah[NROWS * HID];          // layer1 output = layer2 input
__device__ __align__(128) __half g_wh[2][HID * HID];         // [n][k] transposed, hi
__device__ __align__(128) __half g_wl[2][HID * HID];         // lo residual
__device__ __align__(128) float g_part[4][NROWS];            // per-n-tile W3 partial sums

// ---------------- helpers ----------------
__device__ __forceinline__ uint32_t smem_u32(const void* p) {
    return (uint32_t)__cvta_generic_to_shared(p);
}
__device__ __forceinline__ void cp16(uint32_t dst, const void* src) {
    asm volatile("cp.async.cg.shared.global [%0], [%1], 16;" :: "r"(dst), "l"(src));
}
#define CP_COMMIT() asm volatile("cp.async.commit_group;")
#define CP_WAIT(n)  asm volatile("cp.async.wait_group %0;" :: "n"(n))

__device__ __forceinline__ uint32_t swz(uint32_t o) { return o ^ ((o >> 3) & 0x70); }

__device__ __forceinline__ void ldsm4(uint32_t& r0, uint32_t& r1, uint32_t& r2, uint32_t& r3,
                                      uint32_t addr) {
    asm volatile("ldmatrix.sync.aligned.m8n8.x4.shared.b16 {%0,%1,%2,%3}, [%4];"
                 : "=r"(r0), "=r"(r1), "=r"(r2), "=r"(r3) : "r"(addr));
}
__device__ __forceinline__ void mma16816(float* c, const uint32_t* a, uint32_t b0, uint32_t b1) {
    asm volatile("mma.sync.aligned.m16n8k16.row.col.f32.f16.f16.f32 "
                 "{%0,%1,%2,%3}, {%4,%5,%6,%7}, {%8,%9}, {%0,%1,%2,%3};"
                 : "+f"(c[0]), "+f"(c[1]), "+f"(c[2]), "+f"(c[3])
                 : "r"(a[0]), "r"(a[1]), "r"(a[2]), "r"(a[3]), "r"(b0), "r"(b1));
}

// ---------------- prep: split+transpose W1/W2 to fp16 hi/lo ----------------
__global__ void prep_w_kernel(const float* __restrict__ W1, const float* __restrict__ W2) {
    int n = blockIdx.x & 511;
    int which = blockIdx.x >> 9;
    const float* W = which ? W2 : W1;
    for (int k = threadIdx.x; k < HID; k += blockDim.x) {
        float w = W[k * HID + n];
        __half h = __float2half(w);
        g_wh[which][n * HID + k] = h;
        g_wl[which][n * HID + k] = __float2half(w - __half2float(h));
    }
}

// ---------------- proj: hx = x@Wx + b0, hy = y@Wy ----------------
__global__ void __launch_bounds__(128, 8) proj_kernel(
    const float* __restrict__ x, const float* __restrict__ y,
    const float* __restrict__ Wx, const float* __restrict__ Wy,
    const float* __restrict__ b0)
{
    __shared__ float sx[128];
    const int b = blockIdx.x, tid = threadIdx.x;
    const float* src; const float* W; float* dst; bool addb;
    if (b < BSZ) { src = x + b * 128;         W = Wx; dst = g_hx + b * HID;         addb = true;  }
    else         { src = y + (b - BSZ) * 128; W = Wy; dst = g_hy + (b - BSZ) * HID; addb = false; }
    sx[tid] = src[tid];
    __syncthreads();
    const float4* W4 = (const float4*)W;
    float4 acc = make_float4(0.f, 0.f, 0.f, 0.f);
#pragma unroll 8
    for (int k = 0; k < 128; ++k) {
        float xv = sx[k];
        float4 w = W4[k * (HID / 4) + tid];
        acc.x = fmaf(xv, w.x, acc.x); acc.y = fmaf(xv, w.y, acc.y);
        acc.z = fmaf(xv, w.z, acc.z); acc.w = fmaf(xv, w.w, acc.w);
    }
    if (addb) {
        float4 bb = ((const float4*)b0)[tid];
        acc.x += bb.x; acc.y += bb.y; acc.z += bb.z; acc.w += bb.w;
    }
    ((float4*)dst)[tid] = acc;
}

// ---------------- GEMM layer (templated): fused h0 (FIRST) / fused W3 dot (LAST) ----------------
template<bool FIRST, bool LAST>
__global__ void __launch_bounds__(256, 2) layer_kernel(const float* __restrict__ bias,
                                                       const float* __restrict__ W3)
{
    extern __shared__ __align__(1024) char smem[];
    const uint32_t sbase = smem_u32(smem);
    float* s_hx = (float*)(smem + SMEM_HX);
    const int tid = threadIdx.x, wid = tid >> 5, lane = tid & 31;
    const int warp_m = wid & 1;
    const int warp_n = wid >> 1;
    const int row0 = (blockIdx.x >> 2) * TILE_M;
    const int n0 = (blockIdx.x & 3) * TILE_N;
    const int which = FIRST ? 0 : 1;
    const __half* __restrict__ Whi = g_wh[which];
    const __half* __restrict__ Wlo = g_wl[which];
    const int j0 = row0 & 255;            // FIRST: j range of this tile
    const int iidx = row0 >> 8;           // FIRST: x-row index

    const uint32_t aA = swz((uint32_t)((warp_m * 64 + (lane & 15)) * 128 + ((lane >> 4) & 1) * 16));
    const int nloc = (lane & 7) + ((lane >> 4) << 3);
    const uint32_t aB = swz((uint32_t)((warp_n * 32 + nloc) * 128 + ((lane >> 3) & 1) * 16));

    float acc[4][4][4];
#pragma unroll
    for (int mg = 0; mg < 4; ++mg)
#pragma unroll
        for (int n8 = 0; n8 < 4; ++n8)
#pragma unroll
            for (int c = 0; c < 4; ++c) acc[mg][n8][c] = 0.f;

    auto load_chunk = [&](int t, int s) {
        uint32_t sb = sbase + s * STAGE_BYTES;
        if (FIRST) {
            // A-part computed on the fly: relu(hx + hy) -> fp16 STS
#pragma unroll
            for (int e = 0; e < 4; ++e) {
                int idx = tid + 256 * e;
                int r = idx >> 3, u = idx & 7;
                int k = t * KC + u * 8;
                const float4* hy4 = (const float4*)(g_hy + (size_t)(j0 + r) * HID + k);
                float4 y0 = hy4[0], y1 = hy4[1];
                float4 x0 = *(const float4*)(s_hx + k);
                float4 x1 = *(const float4*)(s_hx + k + 4);
                uint4 val;
                ((__half2*)&val)[0] = __floats2half2_rn(fmaxf(x0.x + y0.x, 0.f), fmaxf(x0.y + y0.y, 0.f));
                ((__half2*)&val)[1] = __floats2half2_rn(fmaxf(x0.z + y0.z, 0.f), fmaxf(x0.w + y0.w, 0.f));
                ((__half2*)&val)[2] = __floats2half2_rn(fmaxf(x1.x + y1.x, 0.f), fmaxf(x1.y + y1.y, 0.f));
                ((__half2*)&val)[3] = __floats2half2_rn(fmaxf(x1.z + y1.z, 0.f), fmaxf(x1.w + y1.w, 0.f));
                *(uint4*)(smem + (size_t)(s * STAGE_BYTES) + swz((uint32_t)(r * 128 + u * 16))) = val;
            }
            // W parts via cp.async: 2048 units / 256 thr = 8 each
#pragma unroll
            for (int e = 0; e < 8; ++e) {
                int idx = tid + 256 * e;
                int part = 1 + (idx >> 10);
                int r = (idx >> 3) & 127, u = idx & 7;
                uint32_t dst = sb + part * 16384 + swz((uint32_t)(r * 128 + u * 16));
                const __half* src = (part == 1) ? Whi : Wlo;
                cp16(dst, src + (size_t)(n0 + r) * HID + t * KC + u * 8);
            }
        } else {
#pragma unroll
            for (int e = 0; e < 12; ++e) {
                int idx = tid + 256 * e;
                int part = idx >> 10;
                int r = (idx >> 3) & 127, u = idx & 7;
                uint32_t dst = sb + part * 16384 + swz((uint32_t)(r * 128 + u * 16));
                const __half* src = (part == 0) ? g_ah : ((part == 1) ? Whi : Wlo);
                int rbase = (part == 0) ? row0 : n0;
                cp16(dst, src + (size_t)(rbase + r) * HID + t * KC + u * 8);
            }
        }
        CP_COMMIT();
    };

    auto do_k16 = [&](uint32_t stg, int k16) {
        const uint32_t ko = (uint32_t)(k16 << 5);
        uint32_t bh[2][4], bl[2][4];
#pragma unroll
        for (int ng = 0; ng < 2; ++ng) {
            uint32_t base = (stg + 16384 + aB + ng * 2048) ^ ko;
            ldsm4(bh[ng][0], bh[ng][1], bh[ng][2], bh[ng][3], base);
            ldsm4(bl[ng][0], bl[ng][1], bl[ng][2], bl[ng][3], base + 16384);
        }
#pragma unroll
        for (int mg = 0; mg < 4; ++mg) {
            uint32_t a[4];
            ldsm4(a[0], a[1], a[2], a[3], (stg + aA + mg * 2048) ^ ko);
#pragma unroll
            for (int ng = 0; ng < 2; ++ng)
#pragma unroll
                for (int j = 0; j < 2; ++j) {
                    float* c = acc[mg][ng * 2 + j];
                    mma16816(c, a, bh[ng][2 * j], bh[ng][2 * j + 1]);
                    mma16816(c, a, bl[ng][2 * j], bl[ng][2 * j + 1]);
                }
        }
    };

    if (FIRST) {
        s_hx[tid]       = g_hx[(size_t)iidx * HID + tid];
        s_hx[tid + 256] = g_hx[(size_t)iidx * HID + tid + 256];
    }
    __syncthreads();
    load_chunk(0, 0);

#pragma unroll 1
    for (int t = 0; t < NCH; ++t) {
        CP_WAIT(0);
        __syncthreads();                 // publishes buf t, retires buf t-1
        const uint32_t stg = sbase + (t & 1) * STAGE_BYTES;
        do_k16(stg, 0);
        if (t + 1 < NCH) load_chunk(t + 1, (t + 1) & 1);
        do_k16(stg, 1);
        do_k16(stg, 2);
        do_k16(stg, 3);
    }

    if (!LAST) {
        // epilogue: bias + relu -> fp16 -> g_ah
#pragma unroll
        for (int n8 = 0; n8 < 4; ++n8) {
            const int col = n0 + warp_n * 32 + n8 * 8 + (lane & 3) * 2;
            float2 bq = *(const float2*)(bias + col);
#pragma unroll
            for (int mg = 0; mg < 4; ++mg) {
                const int row = row0 + warp_m * 64 + mg * 16 + (lane >> 2);
                float* c = acc[mg][n8];
#pragma unroll
                for (int h = 0; h < 2; ++h) {
                    float v0 = fmaxf(c[2 * h]     + bq.x, 0.f);
                    float v1 = fmaxf(c[2 * h + 1] + bq.y, 0.f);
                    *(__half2*)(g_ah + (size_t)(row + h * 8) * HID + col) = __floats2half2_rn(v0, v1);
                }
            }
        }
    } else {
        // epilogue: rowsum += relu(acc + bias) * W3[col]; reduce; partials out
        float rowsum[4][2];
#pragma unroll
        for (int mg = 0; mg < 4; ++mg) { rowsum[mg][0] = 0.f; rowsum[mg][1] = 0.f; }
#pragma unroll
        for (int n8 = 0; n8 < 4; ++n8) {
            const int col = n0 + warp_n * 32 + n8 * 8 + (lane & 3) * 2;
            float2 bq = *(const float2*)(bias + col);
            float2 w3 = *(const float2*)(W3 + col);
#pragma unroll
            for (int mg = 0; mg < 4; ++mg) {
                float* c = acc[mg][n8];
#pragma unroll
                for (int h = 0; h < 2; ++h) {
                    float v0 = fmaxf(c[2 * h]     + bq.x, 0.f);
                    float v1 = fmaxf(c[2 * h + 1] + bq.y, 0.f);
                    rowsum[mg][h] = fmaf(v0, w3.x, fmaf(v1, w3.y, rowsum[mg][h]));
                }
            }
        }
        // quad reduce (lane&3 varies cols only)
#pragma unroll
        for (int mg = 0; mg < 4; ++mg)
#pragma unroll
            for (int h = 0; h < 2; ++h) {
                rowsum[mg][h] += __shfl_xor_sync(0xffffffffu, rowsum[mg][h], 1);
                rowsum[mg][h] += __shfl_xor_sync(0xffffffffu, rowsum[mg][h], 2);
            }
        // deterministic cross-warp_n reduce via SMEM staging
        float* s_part = (float*)smem;        // [4][128]
        __syncthreads();                     // all compute done; stages reusable
        if ((lane & 3) == 0) {
#pragma unroll
            for (int mg = 0; mg < 4; ++mg)
#pragma unroll
                for (int h = 0; h < 2; ++h) {
                    int rl = warp_m * 64 + mg * 16 + (lane >> 2) + h * 8;
                    s_part[warp_n * 128 + rl] = rowsum[mg][h];
                }
        }
        __syncthreads();
        if (tid < 128) {
            float s = s_part[tid] + s_part[128 + tid] + s_part[256 + tid] + s_part[384 + tid];
            g_part[n0 >> 7][row0 + tid] = s;
        }
    }
}

// ---------------- combine: out[r] = sum_nt g_part[nt][r] + b3 ----------------
__global__ void __launch_bounds__(256) combine_kernel(const float* __restrict__ b3,
                                                      float* __restrict__ out) {
    int r = blockIdx.x * 256 + threadIdx.x;
    out[r] = g_part[0][r] + g_part[1][r] + g_part[2][r] + g_part[3][r] + b3[0];
}

// ---------------- launch ----------------
extern "C" void kernel_launch(void* const* d_in, const int* in_sizes, int n_in,
                              void* d_out, int out_size)
{
    const float* x  = (const float*)d_in[0];
    const float* y  = (const float*)d_in[1];
    const float* Wx = (const float*)d_in[2];
    const float* Wy = (const float*)d_in[3];
    const float* b0 = (const float*)d_in[4];
    const float* W1 = (const float*)d_in[5];
    const float* b1 = (const float*)d_in[6];
    const float* W2 = (const float*)d_in[7];
    const float* b2 = (const float*)d_in[8];
    const float* W3 = (const float*)d_in[9];
    const float* b3 = (const float*)d_in[10];
    float* out = (float*)d_out;

    cudaFuncSetAttribute(layer_kernel<true, false>,
                         cudaFuncAttributeMaxDynamicSharedMemorySize, SMEM_BYTES);
    cudaFuncSetAttribute(layer_kernel<false, true>,
                         cudaFuncAttributeMaxDynamicSharedMemorySize, SMEM_BYTES);

    prep_w_kernel<<<1024, 256>>>(W1, W2);
    proj_kernel<<<2 * BSZ, 128>>>(x, y, Wx, Wy, b0);
    layer_kernel<true, false><<<(NROWS / TILE_M) * 4, 256, SMEM_BYTES>>>(b1, nullptr);
    layer_kernel<false, true><<<(NROWS / TILE_M) * 4, 256, SMEM_BYTES>>>(b2, W3);
    combine_kernel<<<NROWS / 256, 256>>>(b3, out);
}

// round 7
// speedup vs baseline: 10.1401x; 1.6110x over previous
#include <cuda_runtime.h>
#include <cuda_fp16.h>
#include <cstdint>

#define HID    512
#define BSZ    256
#define NROWS  (BSZ * BSZ)      // 65536
#define TILE_M 128
#define TILE_N 128
#define KC     64               // k per chunk (128B rows)
#define NCH    (HID / KC)       // 8 chunks

// Stage: A(128x64 fp16)=16K | W(128x64)=16K = 32K; 2 stages; + s_hx 2K
#define STAGE_BYTES 32768
#define SMEM_HX     65536
#define SMEM_BYTES  67584

// ---------------- device scratch ----------------
__device__ __align__(128) float g_hx[BSZ * HID];
__device__ __align__(128) float g_hy[BSZ * HID];
__device__ __align__(128) __half g_ah[NROWS * HID];          // layer1 output = layer2 input
__device__ __align__(128) __half g_wh[2][HID * HID];         // [n][k] transposed fp16
__device__ __align__(128) float g_part[4][NROWS];            // per-n-tile W3 partial sums

// ---------------- helpers ----------------
__device__ __forceinline__ uint32_t smem_u32(const void* p) {
    return (uint32_t)__cvta_generic_to_shared(p);
}
__device__ __forceinline__ void cp16(uint32_t dst, const void* src) {
    asm volatile("cp.async.cg.shared.global [%0], [%1], 16;" :: "r"(dst), "l"(src));
}
#define CP_COMMIT() asm volatile("cp.async.commit_group;")
#define CP_WAIT(n)  asm volatile("cp.async.wait_group %0;" :: "n"(n))

__device__ __forceinline__ uint32_t swz(uint32_t o) { return o ^ ((o >> 3) & 0x70); }

__device__ __forceinline__ void ldsm4(uint32_t& r0, uint32_t& r1, uint32_t& r2, uint32_t& r3,
                                      uint32_t addr) {
    asm volatile("ldmatrix.sync.aligned.m8n8.x4.shared.b16 {%0,%1,%2,%3}, [%4];"
                 : "=r"(r0), "=r"(r1), "=r"(r2), "=r"(r3) : "r"(addr));
}
__device__ __forceinline__ void mma16816(float* c, const uint32_t* a, uint32_t b0, uint32_t b1) {
    asm volatile("mma.sync.aligned.m16n8k16.row.col.f32.f16.f16.f32 "
                 "{%0,%1,%2,%3}, {%4,%5,%6,%7}, {%8,%9}, {%0,%1,%2,%3};"
                 : "+f"(c[0]), "+f"(c[1]), "+f"(c[2]), "+f"(c[3])
                 : "r"(a[0]), "r"(a[1]), "r"(a[2]), "r"(a[3]), "r"(b0), "r"(b1));
}

// ---------------- prep: transpose W1/W2 to fp16 ----------------
__global__ void prep_w_kernel(const float* __restrict__ W1, const float* __restrict__ W2) {
    int n = blockIdx.x & 511;
    int which = blockIdx.x >> 9;
    const float* W = which ? W2 : W1;
    for (int k = threadIdx.x; k < HID; k += blockDim.x)
        g_wh[which][n * HID + k] = __float2half(W[k * HID + n]);
}

// ---------------- proj: hx = x@Wx + b0, hy = y@Wy ----------------
__global__ void __launch_bounds__(128, 8) proj_kernel(
    const float* __restrict__ x, const float* __restrict__ y,
    const float* __restrict__ Wx, const float* __restrict__ Wy,
    const float* __restrict__ b0)
{
    __shared__ float sx[128];
    const int b = blockIdx.x, tid = threadIdx.x;
    const float* src; const float* W; float* dst; bool addb;
    if (b < BSZ) { src = x + b * 128;         W = Wx; dst = g_hx + b * HID;         addb = true;  }
    else         { src = y + (b - BSZ) * 128; W = Wy; dst = g_hy + (b - BSZ) * HID; addb = false; }
    sx[tid] = src[tid];
    __syncthreads();
    const float4* W4 = (const float4*)W;
    float4 acc = make_float4(0.f, 0.f, 0.f, 0.f);
#pragma unroll 8
    for (int k = 0; k < 128; ++k) {
        float xv = sx[k];
        float4 w = W4[k * (HID / 4) + tid];
        acc.x = fmaf(xv, w.x, acc.x); acc.y = fmaf(xv, w.y, acc.y);
        acc.z = fmaf(xv, w.z, acc.z); acc.w = fmaf(xv, w.w, acc.w);
    }
    if (addb) {
        float4 bb = ((const float4*)b0)[tid];
        acc.x += bb.x; acc.y += bb.y; acc.z += bb.z; acc.w += bb.w;
    }
    ((float4*)dst)[tid] = acc;
}

// ---------------- GEMM layer (templated): fused h0 (FIRST) / fused W3 dot (LAST) ----------------
template<bool FIRST, bool LAST>
__global__ void __launch_bounds__(256, 2) layer_kernel(const float* __restrict__ bias,
                                                       const float* __restrict__ W3)
{
    extern __shared__ __align__(1024) char smem[];
    const uint32_t sbase = smem_u32(smem);
    float* s_hx = (float*)(smem + SMEM_HX);
    const int tid = threadIdx.x, wid = tid >> 5, lane = tid & 31;
    const int warp_m = wid & 1;
    const int warp_n = wid >> 1;
    const int row0 = (blockIdx.x >> 2) * TILE_M;
    const int n0 = (blockIdx.x & 3) * TILE_N;
    const int which = FIRST ? 0 : 1;
    const __half* __restrict__ Wp = g_wh[which];
    const int j0 = row0 & 255;            // FIRST: j range of this tile
    const int iidx = row0 >> 8;           // FIRST: x-row index

    const uint32_t aA = swz((uint32_t)((warp_m * 64 + (lane & 15)) * 128 + ((lane >> 4) & 1) * 16));
    const int nloc = (lane & 7) + ((lane >> 4) << 3);
    const uint32_t aB = swz((uint32_t)((warp_n * 32 + nloc) * 128 + ((lane >> 3) & 1) * 16));

    float acc[4][4][4];
#pragma unroll
    for (int mg = 0; mg < 4; ++mg)
#pragma unroll
        for (int n8 = 0; n8 < 4; ++n8)
#pragma unroll
            for (int c = 0; c < 4; ++c) acc[mg][n8][c] = 0.f;

    auto load_chunk = [&](int t, int s) {
        uint32_t sb = sbase + s * STAGE_BYTES;
        if (FIRST) {
            // A computed on the fly: relu(hx + hy) -> fp16 STS
#pragma unroll
            for (int e = 0; e < 4; ++e) {
                int idx = tid + 256 * e;
                int r = idx >> 3, u = idx & 7;
                int k = t * KC + u * 8;
                const float4* hy4 = (const float4*)(g_hy + (size_t)(j0 + r) * HID + k);
                float4 y0 = hy4[0], y1 = hy4[1];
                float4 x0 = *(const float4*)(s_hx + k);
                float4 x1 = *(const float4*)(s_hx + k + 4);
                uint4 val;
                ((__half2*)&val)[0] = __floats2half2_rn(fmaxf(x0.x + y0.x, 0.f), fmaxf(x0.y + y0.y, 0.f));
                ((__half2*)&val)[1] = __floats2half2_rn(fmaxf(x0.z + y0.z, 0.f), fmaxf(x0.w + y0.w, 0.f));
                ((__half2*)&val)[2] = __floats2half2_rn(fmaxf(x1.x + y1.x, 0.f), fmaxf(x1.y + y1.y, 0.f));
                ((__half2*)&val)[3] = __floats2half2_rn(fmaxf(x1.z + y1.z, 0.f), fmaxf(x1.w + y1.w, 0.f));
                *(uint4*)(smem + (size_t)(s * STAGE_BYTES) + swz((uint32_t)(r * 128 + u * 16))) = val;
            }
            // W via cp.async: 1024 units / 256 thr = 4 each
#pragma unroll
            for (int e = 0; e < 4; ++e) {
                int idx = tid + 256 * e;
                int r = idx >> 3, u = idx & 7;
                uint32_t dst = sb + 16384 + swz((uint32_t)(r * 128 + u * 16));
                cp16(dst, Wp + (size_t)(n0 + r) * HID + t * KC + u * 8);
            }
        } else {
            // A + W via cp.async: 2048 units / 256 thr = 8 each
#pragma unroll
            for (int e = 0; e < 8; ++e) {
                int idx = tid + 256 * e;
                int part = idx >> 10;            // 0:A 1:W
                int r = (idx >> 3) & 127, u = idx & 7;
                uint32_t dst = sb + part * 16384 + swz((uint32_t)(r * 128 + u * 16));
                const __half* src = (part == 0) ? g_ah : Wp;
                int rbase = (part == 0) ? row0 : n0;
                cp16(dst, src + (size_t)(rbase + r) * HID + t * KC + u * 8);
            }
        }
        CP_COMMIT();
    };

    auto do_k16 = [&](uint32_t stg, int k16) {
        const uint32_t ko = (uint32_t)(k16 << 5);
        uint32_t bh[2][4];
#pragma unroll
        for (int ng = 0; ng < 2; ++ng) {
            uint32_t base = (stg + 16384 + aB + ng * 2048) ^ ko;
            ldsm4(bh[ng][0], bh[ng][1], bh[ng][2], bh[ng][3], base);
        }
#pragma unroll
        for (int mg = 0; mg < 4; ++mg) {
            uint32_t a[4];
            ldsm4(a[0], a[1], a[2], a[3], (stg + aA + mg * 2048) ^ ko);
#pragma unroll
            for (int ng = 0; ng < 2; ++ng)
#pragma unroll
                for (int j = 0; j < 2; ++j)
                    mma16816(acc[mg][ng * 2 + j], a, bh[ng][2 * j], bh[ng][2 * j + 1]);
        }
    };

    if (FIRST) {
        s_hx[tid]       = g_hx[(size_t)iidx * HID + tid];
        s_hx[tid + 256] = g_hx[(size_t)iidx * HID + tid + 256];
    }
    __syncthreads();
    load_chunk(0, 0);

#pragma unroll 1
    for (int t = 0; t < NCH; ++t) {
        CP_WAIT(0);
        __syncthreads();                 // publishes buf t, retires buf t-1
        const uint32_t stg = sbase + (t & 1) * STAGE_BYTES;
        do_k16(stg, 0);
        if (t + 1 < NCH) load_chunk(t + 1, (t + 1) & 1);
        do_k16(stg, 1);
        do_k16(stg, 2);
        do_k16(stg, 3);
    }

    if (!LAST) {
        // epilogue: bias + relu -> fp16 -> g_ah
#pragma unroll
        for (int n8 = 0; n8 < 4; ++n8) {
            const int col = n0 + warp_n * 32 + n8 * 8 + (lane & 3) * 2;
            float2 bq = *(const float2*)(bias + col);
#pragma unroll
            for (int mg = 0; mg < 4; ++mg) {
                const int row = row0 + warp_m * 64 + mg * 16 + (lane >> 2);
                float* c = acc[mg][n8];
#pragma unroll
                for (int h = 0; h < 2; ++h) {
                    float v0 = fmaxf(c[2 * h]     + bq.x, 0.f);
                    float v1 = fmaxf(c[2 * h + 1] + bq.y, 0.f);
                    *(__half2*)(g_ah + (size_t)(row + h * 8) * HID + col) = __floats2half2_rn(v0, v1);
                }
            }
        }
    } else {
        // epilogue: rowsum += relu(acc + bias) * W3[col]; reduce; partials out
        float rowsum[4][2];
#pragma unroll
        for (int mg = 0; mg < 4; ++mg) { rowsum[mg][0] = 0.f; rowsum[mg][1] = 0.f; }
#pragma unroll
        for (int n8 = 0; n8 < 4; ++n8) {
            const int col = n0 + warp_n * 32 + n8 * 8 + (lane & 3) * 2;
            float2 bq = *(const float2*)(bias + col);
            float2 w3 = *(const float2*)(W3 + col);
#pragma unroll
            for (int mg = 0; mg < 4; ++mg) {
                float* c = acc[mg][n8];
#pragma unroll
                for (int h = 0; h < 2; ++h) {
                    float v0 = fmaxf(c[2 * h]     + bq.x, 0.f);
                    float v1 = fmaxf(c[2 * h + 1] + bq.y, 0.f);
                    rowsum[mg][h] = fmaf(v0, w3.x, fmaf(v1, w3.y, rowsum[mg][h]));
                }
            }
        }
#pragma unroll
        for (int mg = 0; mg < 4; ++mg)
#pragma unroll
            for (int h = 0; h < 2; ++h) {
                rowsum[mg][h] += __shfl_xor_sync(0xffffffffu, rowsum[mg][h], 1);
                rowsum[mg][h] += __shfl_xor_sync(0xffffffffu, rowsum[mg][h], 2);
            }
        float* s_part = (float*)smem;        // [4][128]
        __syncthreads();
        if ((lane & 3) == 0) {
#pragma unroll
            for (int mg = 0; mg < 4; ++mg)
#pragma unroll
                for (int h = 0; h < 2; ++h) {
                    int rl = warp_m * 64 + mg * 16 + (lane >> 2) + h * 8;
                    s_part[warp_n * 128 + rl] = rowsum[mg][h];
                }
        }
        __syncthreads();
        if (tid < 128) {
            float s = s_part[tid] + s_part[128 + tid] + s_part[256 + tid] + s_part[384 + tid];
            g_part[n0 >> 7][row0 + tid] = s;
        }
    }
}

// ---------------- combine: out[r] = sum_nt g_part[nt][r] + b3 ----------------
__global__ void __launch_bounds__(256) combine_kernel(const float* __restrict__ b3,
                                                      float* __restrict__ out) {
    int r = blockIdx.x * 256 + threadIdx.x;
    out[r] = g_part[0][r] + g_part[1][r] + g_part[2][r] + g_part[3][r] + b3[0];
}

// ---------------- launch ----------------
extern "C" void kernel_launch(void* const* d_in, const int* in_sizes, int n_in,
                              void* d_out, int out_size)
{
    const float* x  = (const float*)d_in[0];
    const float* y  = (const float*)d_in[1];
    const float* Wx = (const float*)d_in[2];
    const float* Wy = (const float*)d_in[3];
    const float* b0 = (const float*)d_in[4];
    const float* W1 = (const float*)d_in[5];
    const float* b1 = (const float*)d_in[6];
    const float* W2 = (const float*)d_in[7];
    const float* b2 = (const float*)d_in[8];
    const float* W3 = (const float*)d_in[9];
    const float* b3 = (const float*)d_in[10];
    float* out = (float*)d_out;

    cudaFuncSetAttribute(layer_kernel<true, false>,
                         cudaFuncAttributeMaxDynamicSharedMemorySize, SMEM_BYTES);
    cudaFuncSetAttribute(layer_kernel<false, true>,
                         cudaFuncAttributeMaxDynamicSharedMemorySize, SMEM_BYTES);

    prep_w_kernel<<<1024, 256>>>(W1, W2);
    proj_kernel<<<2 * BSZ, 128>>>(x, y, Wx, Wy, b0);
    layer_kernel<true, false><<<(NROWS / TILE_M) * 4, 256, SMEM_BYTES>>>(b1, nullptr);
    layer_kernel<false, true><<<(NROWS / TILE_M) * 4, 256, SMEM_BYTES>>>(b2, W3);
    combine_kernel<<<NROWS / 256, 256>>>(b3, out);
}